// round 8
// baseline (speedup 1.0000x reference)
#include <cuda_runtime.h>
#include <math.h>
#include <float.h>

#define NN 50000
#define EE 400000
#define DH 128
#define DE 32
#define NH 8
#define CH 16

typedef unsigned long long ull;

// ---------------- scratch (device globals: no allocation allowed) ----------------
__device__ float g_q[(size_t)NN * DH];
__device__ float g_k[(size_t)NN * DH];
__device__ float g_v[(size_t)NN * DH];
__device__ float g_agg[(size_t)NN * DH];
__device__ float g_feat[(size_t)NN * DH];
__device__ float g_e[(size_t)EE * DH];          // edge projection, CSR-PERMUTED order
__device__ float g_raw[(size_t)EE * NH];        // raw logits, CSR-PERMUTED order
// CSR (built once per call)
__device__ int g_deg[NN];
__device__ int g_fill[NN];
__device__ int g_rowptr[NN + 1];
__device__ int g_eperm[EE];                     // permuted pos -> original edge id

// ---------------- packed f32x2 helpers (2x fp32 FMA rate on sm_103a) -------------
__device__ __forceinline__ ull pk2(float lo, float hi) {
    ull r; asm("mov.b64 %0, {%1, %2};" : "=l"(r) : "f"(lo), "f"(hi)); return r;
}
__device__ __forceinline__ float2 upk2(ull a) {
    float2 r; asm("mov.b64 {%0, %1}, %2;" : "=f"(r.x), "=f"(r.y) : "l"(a)); return r;
}
__device__ __forceinline__ ull ffma2(ull a, ull b, ull c) {
    ull d; asm("fma.rn.f32x2 %0, %1, %2, %3;" : "=l"(d) : "l"(a), "l"(b), "l"(c)); return d;
}
__device__ __forceinline__ ull fadd2(ull a, ull b) {
    ull d; asm("add.rn.f32x2 %0, %1, %2;" : "=l"(d) : "l"(a), "l"(b)); return d;
}

// ---------------- fused 4-way node projection GEMM (unchanged, known-good) -------
#define BN 64
#define WPAD 132
#define PROJ_THREADS 256
#define PROJ_SMEM ((BN * DH + DH * WPAD) * 4)

__global__ void proj_kernel(const float* __restrict__ hin,
                            const float* __restrict__ Wq, const float* __restrict__ bq,
                            const float* __restrict__ Wk, const float* __restrict__ bk,
                            const float* __restrict__ Wv, const float* __restrict__ bv,
                            const float* __restrict__ Ws, const float* __restrict__ bs) {
    extern __shared__ float sh[];
    float* xs  = sh;             // [BN][DH]
    float* wsT = sh + BN * DH;   // [DH][WPAD]
    const int tid = threadIdx.x;
    const int node0 = blockIdx.x * BN;

    for (int i = tid; i < BN * DH / 4; i += PROJ_THREADS) {
        int n  = i / (DH / 4);
        int c4 = (i % (DH / 4)) * 4;
        float4 v = make_float4(0.f, 0.f, 0.f, 0.f);
        if (node0 + n < NN) v = *(const float4*)(hin + (size_t)(node0 + n) * DH + c4);
        *(float4*)(xs + n * DH + c4) = v;
    }

    const int cgrp = tid & 31;
    const int ngrp = tid >> 5;
    const int c0 = cgrp * 4;

    const float* Wlist[4] = {Wq, Wk, Wv, Ws};
    const float* Blist[4] = {bq, bk, bv, bs};
    float* Olist[4] = {g_q, g_k, g_v, g_agg};

    for (int w = 0; w < 4; ++w) {
        __syncthreads();
        const float* W = Wlist[w];
        for (int t = tid; t < DH * DH; t += PROJ_THREADS) {
            int ch = t >> 7, kk = t & (DH - 1);
            wsT[kk * WPAD + ch] = W[t];
        }
        __syncthreads();

        ull acc0[8], acc1[8];
#pragma unroll
        for (int i = 0; i < 8; ++i) { acc0[i] = 0ULL; acc1[i] = 0ULL; }

        const float* xrow = xs + (ngrp * 8) * DH;
#pragma unroll 8
        for (int kk = 0; kk < DH; ++kk) {
            ulonglong2 wp = *(const ulonglong2*)(wsT + kk * WPAD + c0);
#pragma unroll
            for (int i = 0; i < 8; ++i) {
                float xv = xrow[i * DH + kk];
                ull xx = pk2(xv, xv);
                acc0[i] = ffma2(xx, wp.x, acc0[i]);
                acc1[i] = ffma2(xx, wp.y, acc1[i]);
            }
        }

        float4 bias = *(const float4*)(Blist[w] + c0);
        float* O = Olist[w];
#pragma unroll
        for (int i = 0; i < 8; ++i) {
            int n = node0 + ngrp * 8 + i;
            if (n < NN) {
                float2 a = upk2(acc0[i]), b = upk2(acc1[i]);
                float4 o = make_float4(a.x + bias.x, a.y + bias.y, b.x + bias.z, b.y + bias.w);
                *(float4*)(O + (size_t)n * DH + c0) = o;
            }
        }
    }
}

// ---------------- CSR build (once per call) ---------------------------------------
__global__ void csr_zero_kernel() {
    int i = blockIdx.x * blockDim.x + threadIdx.x;
    if (i < NN) { g_deg[i] = 0; g_fill[i] = 0; }
}
__global__ void csr_hist_kernel(const int* __restrict__ eidx) {
    int i = blockIdx.x * blockDim.x + threadIdx.x;
    if (i < EE) atomicAdd(&g_deg[eidx[EE + i]], 1);
}
__global__ void csr_scan_kernel() {
    __shared__ int sh[1024];
    __shared__ int carry;
    const int tid = threadIdx.x;
    if (tid == 0) carry = 0;
    __syncthreads();
    for (int base = 0; base < NN; base += 1024) {
        int v = (base + tid < NN) ? g_deg[base + tid] : 0;
        sh[tid] = v;
        __syncthreads();
        for (int off = 1; off < 1024; off <<= 1) {
            int t = (tid >= off) ? sh[tid - off] : 0;
            __syncthreads();
            sh[tid] += t;
            __syncthreads();
        }
        if (base + tid < NN) g_rowptr[base + tid] = carry + sh[tid] - v;
        __syncthreads();
        if (tid == 0) carry += sh[1023];
        __syncthreads();
    }
    if (tid == 0) g_rowptr[NN] = carry;   // == EE
}
__global__ void csr_scatter_kernel(const int* __restrict__ eidx) {
    int i = blockIdx.x * blockDim.x + threadIdx.x;
    if (i >= EE) return;
    int dst = eidx[EE + i];
    int pos = g_rowptr[dst] + atomicAdd(&g_fill[dst], 1);
    g_eperm[pos] = i;
}

// ---------------- fused edge projection + logit (warp per permuted edge) ----------
// For permuted pos p: o = eperm[p]; e = We @ ef[o]; write g_e[p] (sequential);
// logit = q[dst]·(k[src]+e)/4 -> g_raw[p] (sequential).
__global__ void eprojA_kernel(const float* __restrict__ We, const float* __restrict__ ef,
                              const int* __restrict__ eidx) {
    __shared__ float ws[DE][WPAD];   // ws[k][c] = We[c][k]
    const int tid = threadIdx.x;
    for (int t = tid; t < DH * DE; t += 256) {
        int c = t >> 5, k = t & (DE - 1);
        ws[k][c] = We[t];
    }
    __syncthreads();

    const int lane = tid & 31;
    const int p = blockIdx.x * 8 + (tid >> 5);
    if (p >= EE) return;
    const int o = g_eperm[p];
    const int src = eidx[o], dst = eidx[EE + o];

    // gather edge feature row (32 floats, one per lane)
    float efv = ef[(size_t)o * DE + lane];

    // e projection: lane owns channels [lane*4, lane*4+4)
    ull e0 = 0ULL, e1 = 0ULL;
#pragma unroll
    for (int k = 0; k < DE; ++k) {
        float efk = __shfl_sync(0xffffffffu, efv, k);
        ull xx = pk2(efk, efk);
        ulonglong2 w2 = *(const ulonglong2*)(&ws[k][lane * 4]);  // 16B stride: conflict-free
        e0 = ffma2(xx, w2.x, e0);
        e1 = ffma2(xx, w2.y, e1);
    }

    // logit: q[dst] . (k[src] + e)
    ulonglong2 q2 = *(const ulonglong2*)(g_q + (size_t)dst * DH + lane * 4);
    ulonglong2 k2 = *(const ulonglong2*)(g_k + (size_t)src * DH + lane * 4);
    ull acc = ffma2(q2.x, fadd2(k2.x, e0), 0ULL);
    acc = ffma2(q2.y, fadd2(k2.y, e1), acc);
    float2 rr = upk2(acc);
    float r = rr.x + rr.y;
    r += __shfl_xor_sync(0xffffffffu, r, 1);
    r += __shfl_xor_sync(0xffffffffu, r, 2);   // per-head dot (head = lane>>2)

    // store e row (coalesced 512B) + 8 logits (coalesced 32B)
    float2 a = upk2(e0), b = upk2(e1);
    *(float4*)(g_e + (size_t)p * DH + lane * 4) = make_float4(a.x, a.y, b.x, b.y);
    if ((lane & 3) == 0) g_raw[(size_t)p * NH + (lane >> 2)] = r * 0.25f;
}

// ---------------- fused segment softmax + aggregate (warp per destination) --------
// raw/g_e are position-indexed -> pass 1 is shfl-free and fully sequential.
__global__ void edgeC_kernel(const int* __restrict__ eidx, float* __restrict__ alpha_out) {
    const int gw = (blockIdx.x * 256 + threadIdx.x) >> 5;
    const int lane = threadIdx.x & 31;
    if (gw >= NN) return;
    const int d = gw;
    const int p0 = g_rowptr[d];
    const int deg = g_rowptr[d + 1] - p0;
    if (deg == 0) return;

    // warp-preload up to 32 original ids + src ids
    int oL = -1, srcL = -1;
    if (lane < deg) { oL = g_eperm[p0 + lane]; srcL = eidx[oL]; }

    // ---- pass 1: online softmax stats (sequential raw reads, no shfl) ----
    const int h = lane & 7, slot = lane >> 3;
    float m = -FLT_MAX, s = 0.f;
    for (int i = slot; i < deg; i += 4) {
        float r = g_raw[(size_t)(p0 + i) * NH + h];
        float nm = fmaxf(m, r);
        s = s * __expf(m - nm) + __expf(r - nm);
        m = nm;
    }
#pragma unroll
    for (int off = 8; off < 32; off <<= 1) {
        float mo = __shfl_xor_sync(0xffffffffu, m, off);
        float so = __shfl_xor_sync(0xffffffffu, s, off);
        float nm = fmaxf(m, mo);
        s = s * __expf(m - nm) + so * __expf(mo - nm);
        m = nm;
    }

    // redistribute stats to pass-2 lane layout
    const int h2 = lane >> 2, q = lane & 3;
    float mh = __shfl_sync(0xffffffffu, m, h2);
    float sh = __shfl_sync(0xffffffffu, s, h2);
    float inv = 1.f / (sh + 1e-16f);

    // ---- pass 2: accumulate (v+e)*alpha; g_e/raw sequential, v gathered ----
    float4 acc = make_float4(0.f, 0.f, 0.f, 0.f);
    for (int i = 0; i < deg; ++i) {
        int p = p0 + i;
        int o, src;
        if (i < 32) {
            o = __shfl_sync(0xffffffffu, oL, i);
            src = __shfl_sync(0xffffffffu, srcL, i);
        } else {
            o = g_eperm[p];
            src = eidx[o];
        }
        float r = g_raw[(size_t)p * NH + h2];
        float a = __expf(r - mh) * inv;
        float4 v4 = *(const float4*)(g_v + (size_t)src * DH + lane * 4);
        float4 e4 = *(const float4*)(g_e + (size_t)p   * DH + lane * 4);
        acc.x += (v4.x + e4.x) * a;
        acc.y += (v4.y + e4.y) * a;
        acc.z += (v4.z + e4.z) * a;
        acc.w += (v4.w + e4.w) * a;
        if (q == 0) alpha_out[(size_t)o * NH + h2] = a;
    }

    float4 skip = *(const float4*)(g_agg + (size_t)d * DH + lane * 4);
    acc.x += skip.x; acc.y += skip.y; acc.z += skip.z; acc.w += skip.w;
    *(float4*)(g_agg + (size_t)d * DH + lane * 4) = acc;
}

// ---------------- epilogue: exact-erf GELU + feature handoff ----------------------
__global__ void finish_kernel(float* __restrict__ dst, int apply_gelu) {
    int i = blockIdx.x * blockDim.x + threadIdx.x;
    if (i >= NN * DH) return;
    float x = g_agg[i];
    if (apply_gelu) x = x * normcdff(x);   // 0.5*x*(1+erf(x/sqrt(2)))
    dst[i] = x;
}

// ---------------- launch ----------------------------------------------------------
extern "C" void kernel_launch(void* const* d_in, const int* in_sizes, int n_in,
                              void* d_out, int out_size) {
    const float* x   = (const float*)d_in[0];
    const float* ef  = (const float*)d_in[1];
    const float* Wq  = (const float*)d_in[2];
    const float* bq  = (const float*)d_in[3];
    const float* Wk  = (const float*)d_in[4];
    const float* bk  = (const float*)d_in[5];
    const float* Wv  = (const float*)d_in[6];
    const float* bv  = (const float*)d_in[7];
    const float* We  = (const float*)d_in[8];
    const float* Ws  = (const float*)d_in[9];
    const float* bs  = (const float*)d_in[10];
    const int* eidx  = (const int*)d_in[11];
    float* out = (float*)d_out;

    cudaFuncSetAttribute(proj_kernel, cudaFuncAttributeMaxDynamicSharedMemorySize, PROJ_SMEM);
    float* feat = nullptr;
    cudaGetSymbolAddress((void**)&feat, g_feat);

    const int nproj = (NN + BN - 1) / BN;

    // CSR build: once per call, reused by all 4 layers
    csr_zero_kernel<<<(NN + 255) / 256, 256>>>();
    csr_hist_kernel<<<(EE + 255) / 256, 256>>>(eidx);
    csr_scan_kernel<<<1, 1024>>>();
    csr_scatter_kernel<<<(EE + 255) / 256, 256>>>(eidx);

    for (int l = 0; l < 4; ++l) {
        const float* hin = (l == 0) ? x : feat;
        size_t off2 = (size_t)l * DH * DH;
        size_t offb = (size_t)l * DH;
        size_t offe = (size_t)l * DH * DE;

        proj_kernel<<<nproj, PROJ_THREADS, PROJ_SMEM>>>(hin,
            Wq + off2, bq + offb, Wk + off2, bk + offb,
            Wv + off2, bv + offb, Ws + off2, bs + offb);
        eprojA_kernel<<<(EE + 7) / 8, 256>>>(We + offe, ef, eidx);
        edgeC_kernel<<<(NN * 32 + 255) / 256, 256>>>(eidx,
            out + (size_t)NN * DH + (size_t)l * EE * NH);
        finish_kernel<<<(NN * DH + 255) / 256, 256>>>((l == 3) ? out : feat, (l < 3) ? 1 : 0);
    }
}

// round 10
// speedup vs baseline: 1.1355x; 1.1355x over previous
#include <cuda_runtime.h>
#include <math.h>
#include <float.h>

#define NN 50000
#define EE 400000
#define DH 128
#define DE 32
#define NH 8
#define CH 16

typedef unsigned long long ull;

// ---------------- scratch (device globals: no allocation allowed) ----------------
__device__ float g_q[(size_t)NN * DH];
__device__ float g_k[(size_t)NN * DH];
__device__ float g_v[(size_t)NN * DH];
__device__ float g_agg[(size_t)NN * DH];        // skip projection per layer
__device__ float g_feat[(size_t)NN * DH];
__device__ float g_e[(size_t)EE * DH];          // edge projection, CSR-PERMUTED order
__device__ float g_raw[(size_t)EE * NH];        // raw logits, CSR-PERMUTED order
// CSR (built once per call)
__device__ int g_deg[NN];
__device__ int g_fill[NN];
__device__ int g_rowptr[NN + 1];
__device__ int g_eperm[EE];                     // permuted pos -> original edge id

// ---------------- packed f32x2 helpers (2x fp32 FMA rate on sm_103a) -------------
__device__ __forceinline__ ull pk2(float lo, float hi) {
    ull r; asm("mov.b64 %0, {%1, %2};" : "=l"(r) : "f"(lo), "f"(hi)); return r;
}
__device__ __forceinline__ float2 upk2(ull a) {
    float2 r; asm("mov.b64 {%0, %1}, %2;" : "=f"(r.x), "=f"(r.y) : "l"(a)); return r;
}
__device__ __forceinline__ ull ffma2(ull a, ull b, ull c) {
    ull d; asm("fma.rn.f32x2 %0, %1, %2, %3;" : "=l"(d) : "l"(a), "l"(b), "l"(c)); return d;
}
__device__ __forceinline__ ull fadd2(ull a, ull b) {
    ull d; asm("add.rn.f32x2 %0, %1, %2;" : "=l"(d) : "l"(a), "l"(b)); return d;
}

// ---------------- fused 4-way node projection GEMM (unchanged, known-good) -------
#define BN 64
#define WPAD 132
#define PROJ_THREADS 256
#define PROJ_SMEM ((BN * DH + DH * WPAD) * 4)

__global__ void proj_kernel(const float* __restrict__ hin,
                            const float* __restrict__ Wq, const float* __restrict__ bq,
                            const float* __restrict__ Wk, const float* __restrict__ bk,
                            const float* __restrict__ Wv, const float* __restrict__ bv,
                            const float* __restrict__ Ws, const float* __restrict__ bs) {
    extern __shared__ float sh[];
    float* xs  = sh;             // [BN][DH]
    float* wsT = sh + BN * DH;   // [DH][WPAD]
    const int tid = threadIdx.x;
    const int node0 = blockIdx.x * BN;

    for (int i = tid; i < BN * DH / 4; i += PROJ_THREADS) {
        int n  = i / (DH / 4);
        int c4 = (i % (DH / 4)) * 4;
        float4 v = make_float4(0.f, 0.f, 0.f, 0.f);
        if (node0 + n < NN) v = *(const float4*)(hin + (size_t)(node0 + n) * DH + c4);
        *(float4*)(xs + n * DH + c4) = v;
    }

    const int cgrp = tid & 31;
    const int ngrp = tid >> 5;
    const int c0 = cgrp * 4;

    const float* Wlist[4] = {Wq, Wk, Wv, Ws};
    const float* Blist[4] = {bq, bk, bv, bs};
    float* Olist[4] = {g_q, g_k, g_v, g_agg};

    for (int w = 0; w < 4; ++w) {
        __syncthreads();
        const float* W = Wlist[w];
        for (int t = tid; t < DH * DH; t += PROJ_THREADS) {
            int ch = t >> 7, kk = t & (DH - 1);
            wsT[kk * WPAD + ch] = W[t];
        }
        __syncthreads();

        ull acc0[8], acc1[8];
#pragma unroll
        for (int i = 0; i < 8; ++i) { acc0[i] = 0ULL; acc1[i] = 0ULL; }

        const float* xrow = xs + (ngrp * 8) * DH;
#pragma unroll 8
        for (int kk = 0; kk < DH; ++kk) {
            ulonglong2 wp = *(const ulonglong2*)(wsT + kk * WPAD + c0);
#pragma unroll
            for (int i = 0; i < 8; ++i) {
                float xv = xrow[i * DH + kk];
                ull xx = pk2(xv, xv);
                acc0[i] = ffma2(xx, wp.x, acc0[i]);
                acc1[i] = ffma2(xx, wp.y, acc1[i]);
            }
        }

        float4 bias = *(const float4*)(Blist[w] + c0);
        float* O = Olist[w];
#pragma unroll
        for (int i = 0; i < 8; ++i) {
            int n = node0 + ngrp * 8 + i;
            if (n < NN) {
                float2 a = upk2(acc0[i]), b = upk2(acc1[i]);
                float4 o = make_float4(a.x + bias.x, a.y + bias.y, b.x + bias.z, b.y + bias.w);
                *(float4*)(O + (size_t)n * DH + c0) = o;
            }
        }
    }
}

// ---------------- CSR build (once per call) ---------------------------------------
__global__ void csr_zero_kernel() {
    int i = blockIdx.x * blockDim.x + threadIdx.x;
    if (i < NN) { g_deg[i] = 0; g_fill[i] = 0; }
}
__global__ void csr_hist_kernel(const int* __restrict__ eidx) {
    int i = blockIdx.x * blockDim.x + threadIdx.x;
    if (i < EE) atomicAdd(&g_deg[eidx[EE + i]], 1);
}
__global__ void csr_scan_kernel() {
    __shared__ int sh[1024];
    __shared__ int carry;
    const int tid = threadIdx.x;
    if (tid == 0) carry = 0;
    __syncthreads();
    for (int base = 0; base < NN; base += 1024) {
        int v = (base + tid < NN) ? g_deg[base + tid] : 0;
        sh[tid] = v;
        __syncthreads();
        for (int off = 1; off < 1024; off <<= 1) {
            int t = (tid >= off) ? sh[tid - off] : 0;
            __syncthreads();
            sh[tid] += t;
            __syncthreads();
        }
        if (base + tid < NN) g_rowptr[base + tid] = carry + sh[tid] - v;
        __syncthreads();
        if (tid == 0) carry += sh[1023];
        __syncthreads();
    }
    if (tid == 0) g_rowptr[NN] = carry;   // == EE
}
__global__ void csr_scatter_kernel(const int* __restrict__ eidx) {
    int i = blockIdx.x * blockDim.x + threadIdx.x;
    if (i >= EE) return;
    int dst = eidx[EE + i];
    int pos = g_rowptr[dst] + atomicAdd(&g_fill[dst], 1);
    g_eperm[pos] = i;
}

// ---------------- edge projection GEMM over PERMUTED positions --------------------
// g_e[p] = ef[eperm[p]] @ We^T, written sequentially in permuted order.
#define EPB 64
__global__ void eproj_kernel(const float* __restrict__ We, const float* __restrict__ ef) {
    __shared__ float ws[DE][WPAD];      // ws[k][ch] = We[ch][k]
    __shared__ float efs[EPB][DE + 1];
    __shared__ int sperm[EPB];
    const int tid = threadIdx.x;
    const int lane = tid & 31;
    const int wid = tid >> 5;
    const int p0 = blockIdx.x * EPB;

    for (int t = tid; t < DH * DE; t += 256) {
        int ch = t >> 5, k = t & (DE - 1);
        ws[k][ch] = We[t];
    }
    if (tid < EPB) sperm[tid] = g_eperm[p0 + tid];
    __syncthreads();
    // gather 64 random ef rows: one 128B contiguous row per warp iteration
    for (int rr = wid; rr < EPB; rr += 8) {
        efs[rr][lane] = ef[(size_t)sperm[rr] * DE + lane];
    }
    __syncthreads();

    const int egrp = tid >> 5;
    const int cg = tid & 31;
    const int c0 = cg * 4;

    ull acc0[8], acc1[8];
#pragma unroll
    for (int i = 0; i < 8; ++i) { acc0[i] = 0ULL; acc1[i] = 0ULL; }

#pragma unroll
    for (int k = 0; k < DE; ++k) {
        ulonglong2 wp = *(const ulonglong2*)(&ws[k][c0]);
#pragma unroll
        for (int i = 0; i < 8; ++i) {
            float xv = efs[egrp * 8 + i][k];
            ull xx = pk2(xv, xv);
            acc0[i] = ffma2(xx, wp.x, acc0[i]);
            acc1[i] = ffma2(xx, wp.y, acc1[i]);
        }
    }

#pragma unroll
    for (int i = 0; i < 8; ++i) {
        int p = p0 + egrp * 8 + i;
        float2 a = upk2(acc0[i]), b = upk2(acc1[i]);
        *(float4*)(g_e + (size_t)p * DH + c0) = make_float4(a.x, a.y, b.x, b.y);
    }
}

// ---------------- pass A over PERMUTED positions ----------------------------------
// g_raw[p*8+h] = q[dst]·(k[src]+g_e[p])/4 ; g_e read + raw write fully sequential.
__global__ void edgeA_kernel(const int* __restrict__ eidx) {
    int gt = blockIdx.x * 256 + threadIdx.x;
    if (gt >= EE * NH) return;
    int p = gt >> 3, hh = gt & 7;
    int o = g_eperm[p];
    int src = eidx[o], dst = eidx[EE + o];

    const ulonglong2* qp = (const ulonglong2*)(g_q + (size_t)dst * DH + hh * CH);
    const ulonglong2* kp = (const ulonglong2*)(g_k + (size_t)src * DH + hh * CH);
    const ulonglong2* ep = (const ulonglong2*)(g_e + (size_t)p   * DH + hh * CH);

    ull acc = 0ULL;
#pragma unroll
    for (int j = 0; j < 4; ++j) {
        ulonglong2 q2 = qp[j], k2 = kp[j], e2 = ep[j];
        acc = ffma2(q2.x, fadd2(k2.x, e2.x), acc);
        acc = ffma2(q2.y, fadd2(k2.y, e2.y), acc);
    }
    float2 r = upk2(acc);
    g_raw[gt] = (r.x + r.y) * 0.25f;   // / sqrt(C=16)
}

// ---------------- fused segment softmax + aggregate + skip + GELU -----------------
// Warp per destination. g_raw/g_e streams sequential in p. Absorbs finish_kernel.
__global__ void edgeC_kernel(const int* __restrict__ eidx, float* __restrict__ alpha_out,
                             float* __restrict__ outp, int apply_gelu) {
    const int gw = (blockIdx.x * 256 + threadIdx.x) >> 5;
    const int lane = threadIdx.x & 31;
    if (gw >= NN) return;
    const int d = gw;
    const int p0 = g_rowptr[d];
    const int deg = g_rowptr[d + 1] - p0;

    float4 acc = make_float4(0.f, 0.f, 0.f, 0.f);
    const int h2 = lane >> 2, q = lane & 3;

    if (deg > 0) {
        // warp-preload up to 32 original ids + src ids
        int oL = -1, srcL = -1;
        if (lane < deg) { oL = g_eperm[p0 + lane]; srcL = eidx[oL]; }

        // ---- pass 1: online softmax stats (sequential raw reads, no shfl) ----
        const int h = lane & 7, slot = lane >> 3;
        float m = -FLT_MAX, s = 0.f;
        for (int i = slot; i < deg; i += 4) {
            float r = g_raw[(size_t)(p0 + i) * NH + h];
            float nm = fmaxf(m, r);
            s = s * __expf(m - nm) + __expf(r - nm);
            m = nm;
        }
#pragma unroll
        for (int off = 8; off < 32; off <<= 1) {
            float mo = __shfl_xor_sync(0xffffffffu, m, off);
            float so = __shfl_xor_sync(0xffffffffu, s, off);
            float nm = fmaxf(m, mo);
            s = s * __expf(m - nm) + so * __expf(mo - nm);
            m = nm;
        }

        float mh = __shfl_sync(0xffffffffu, m, h2);
        float sh = __shfl_sync(0xffffffffu, s, h2);
        float inv = 1.f / (sh + 1e-16f);

        // ---- pass 2: accumulate (v+e)*alpha; g_e/raw sequential, v gathered ----
        for (int i = 0; i < deg; ++i) {
            int p = p0 + i;
            int o, src;
            if (i < 32) {
                o = __shfl_sync(0xffffffffu, oL, i);
                src = __shfl_sync(0xffffffffu, srcL, i);
            } else {
                o = g_eperm[p];
                src = eidx[o];
            }
            float r = g_raw[(size_t)p * NH + h2];
            float a = __expf(r - mh) * inv;
            float4 v4 = *(const float4*)(g_v + (size_t)src * DH + lane * 4);
            float4 e4 = *(const float4*)(g_e + (size_t)p   * DH + lane * 4);
            acc.x += (v4.x + e4.x) * a;
            acc.y += (v4.y + e4.y) * a;
            acc.z += (v4.z + e4.z) * a;
            acc.w += (v4.w + e4.w) * a;
            if (q == 0) alpha_out[(size_t)o * NH + h2] = a;
        }
    }

    // skip connection + optional exact-erf GELU, direct to layer output
    float4 skip = *(const float4*)(g_agg + (size_t)d * DH + lane * 4);
    acc.x += skip.x; acc.y += skip.y; acc.z += skip.z; acc.w += skip.w;
    if (apply_gelu) {
        acc.x *= normcdff(acc.x);
        acc.y *= normcdff(acc.y);
        acc.z *= normcdff(acc.z);
        acc.w *= normcdff(acc.w);
    }
    *(float4*)(outp + (size_t)d * DH + lane * 4) = acc;
}

// ---------------- launch ----------------------------------------------------------
extern "C" void kernel_launch(void* const* d_in, const int* in_sizes, int n_in,
                              void* d_out, int out_size) {
    const float* x   = (const float*)d_in[0];
    const float* ef  = (const float*)d_in[1];
    const float* Wq  = (const float*)d_in[2];
    const float* bq  = (const float*)d_in[3];
    const float* Wk  = (const float*)d_in[4];
    const float* bk  = (const float*)d_in[5];
    const float* Wv  = (const float*)d_in[6];
    const float* bv  = (const float*)d_in[7];
    const float* We  = (const float*)d_in[8];
    const float* Ws  = (const float*)d_in[9];
    const float* bs  = (const float*)d_in[10];
    const int* eidx  = (const int*)d_in[11];
    float* out = (float*)d_out;

    cudaFuncSetAttribute(proj_kernel, cudaFuncAttributeMaxDynamicSharedMemorySize, PROJ_SMEM);
    float* feat = nullptr;
    cudaGetSymbolAddress((void**)&feat, g_feat);

    const int nproj = (NN + BN - 1) / BN;

    // CSR build: once per call, reused by all 4 layers
    csr_zero_kernel<<<(NN + 255) / 256, 256>>>();
    csr_hist_kernel<<<(EE + 255) / 256, 256>>>(eidx);
    csr_scan_kernel<<<1, 1024>>>();
    csr_scatter_kernel<<<(EE + 255) / 256, 256>>>(eidx);

    for (int l = 0; l < 4; ++l) {
        const float* hin = (l == 0) ? x : feat;
        size_t off2 = (size_t)l * DH * DH;
        size_t offb = (size_t)l * DH;
        size_t offe = (size_t)l * DH * DE;

        proj_kernel<<<nproj, PROJ_THREADS, PROJ_SMEM>>>(hin,
            Wq + off2, bq + offb, Wk + off2, bk + offb,
            Wv + off2, bv + offb, Ws + off2, bs + offb);
        eproj_kernel<<<EE / EPB, 256>>>(We + offe, ef);
        edgeA_kernel<<<(EE * NH) / 256, 256>>>(eidx);
        edgeC_kernel<<<(NN * 32 + 255) / 256, 256>>>(eidx,
            out + (size_t)NN * DH + (size_t)l * EE * NH,
            (l == 3) ? out : feat, (l < 3) ? 1 : 0);
    }
}